// round 14
// baseline (speedup 1.0000x reference)
#include <cuda_runtime.h>
#include <math.h>
#include <stdint.h>

#define N_NODES   100000
#define N_EDGES   1600000
#define HIDDEN    128
#define NUM_RBF   64
#define NF        128
#define CUTOFF    5.0f
#define PI_F      3.14159265358979323846f

typedef unsigned long long u64;

// ---------------------------------------------------------------------------
// Scratch
// ---------------------------------------------------------------------------
__device__ __align__(16) float g_xf [N_NODES * NF];
__device__ __align__(16) float g_agg[N_NODES * NF];
__device__ float g_cnt[N_NODES];

__device__ __forceinline__ float silu_f(float v) {
    return v / (1.0f + __expf(-v));
}
__device__ __forceinline__ int clamp_idx(int v) {
    v = v < 0 ? 0 : v;
    return v >= N_NODES ? N_NODES - 1 : v;
}

// ---- f32x2 helpers ----
__device__ __forceinline__ u64 pack_rep2(float a) {
    u64 r;
    asm("mov.b64 %0, {%1, %1};" : "=l"(r) : "f"(a));
    return r;
}
__device__ __forceinline__ void fma2(u64& d, u64 a, u64 b) {
    asm("fma.rn.f32x2 %0, %1, %2, %0;" : "+l"(d) : "l"(a), "l"(b));
}
__device__ __forceinline__ void unpack2(u64 v, float& lo, float& hi) {
    asm("mov.b64 {%0, %1}, %2;" : "=f"(lo), "=f"(hi) : "l"(v));
}
__device__ __forceinline__ void lds_v2u64(const void* p, u64& x, u64& y) {
    uint32_t addr = (uint32_t)__cvta_generic_to_shared(p);
    asm("ld.shared.v2.u64 {%0, %1}, [%2];" : "=l"(x), "=l"(y) : "r"(addr));
}
__device__ __forceinline__ void red_add_v4(float* addr, float a, float b,
                                           float c, float d) {
    asm volatile("red.global.add.v4.f32 [%0], {%1, %2, %3, %4};"
                 :: "l"(addr), "f"(a), "f"(b), "f"(c), "f"(d)
                 : "memory");
}

// ---------------------------------------------------------------------------
// Kernel 1: zero agg + cnt
// ---------------------------------------------------------------------------
__global__ void zero_kernel() {
    int idx = blockIdx.x * blockDim.x + threadIdx.x;
    int stride = gridDim.x * blockDim.x;
    float4* agg4 = reinterpret_cast<float4*>(g_agg);
    const int n4 = N_NODES * (NF / 4);
    float4 z = make_float4(0.f, 0.f, 0.f, 0.f);
    for (int i = idx; i < n4; i += stride) agg4[i] = z;
    for (int i = idx; i < N_NODES; i += stride) g_cnt[i] = 0.f;
}

// ---------------------------------------------------------------------------
// Kernel 2: in-degree counts
// ---------------------------------------------------------------------------
__global__ void cnt_kernel(const int* __restrict__ edge_index) {
    int idx = blockIdx.x * blockDim.x + threadIdx.x;
    int stride = gridDim.x * blockDim.x;
    for (int e = idx; e < N_EDGES; e += stride) {
        int d = clamp_idx(edge_index[N_EDGES + e]);
        atomicAdd(&g_cnt[d], 1.0f);
    }
}

// ---------------------------------------------------------------------------
// Kernel 3: xf = x @ lin1_w   (FFMA2, R9 version)
// ---------------------------------------------------------------------------
__global__ void xf_kernel(const float* __restrict__ x,
                          const float* __restrict__ lin1_w) {
    extern __shared__ float sm[];
    float* ws = sm;            // 128*128
    float* xs = ws + 16384;    // 32*128

    const int tid = threadIdx.x;
    for (int i = tid; i < 16384 / 4; i += 256)
        reinterpret_cast<float4*>(ws)[i] = reinterpret_cast<const float4*>(lin1_w)[i];
    __syncthreads();

    const int j0 = (tid & 31) * 4;
    const int n0 = (tid >> 5) * 4;

    const int n_tiles = N_NODES / 32;
    for (int t = blockIdx.x; t < n_tiles; t += gridDim.x) {
        const int base = t * 32;
        for (int i = tid; i < 32 * 32; i += 256)
            reinterpret_cast<float4*>(xs)[i] =
                reinterpret_cast<const float4*>(x + base * HIDDEN)[i];
        __syncthreads();

        u64 acc0[4], acc1[4];
        #pragma unroll
        for (int i = 0; i < 4; i++) { acc0[i] = 0ull; acc1[i] = 0ull; }

        #pragma unroll 4
        for (int k4 = 0; k4 < HIDDEN / 4; k4++) {
            u64 wv[8];
            #pragma unroll
            for (int kk = 0; kk < 4; kk++)
                lds_v2u64(&ws[(k4 * 4 + kk) * NF + j0], wv[2*kk], wv[2*kk+1]);
            float4 a4[4];
            #pragma unroll
            for (int i = 0; i < 4; i++)
                a4[i] = *reinterpret_cast<const float4*>(&xs[(n0 + i) * HIDDEN + k4 * 4]);
            #pragma unroll
            for (int kk = 0; kk < 4; kk++) {
                #pragma unroll
                for (int i = 0; i < 4; i++) {
                    float a = (kk == 0) ? a4[i].x : (kk == 1) ? a4[i].y
                             : (kk == 2) ? a4[i].z : a4[i].w;
                    u64 ap = pack_rep2(a);
                    fma2(acc0[i], ap, wv[2*kk]);
                    fma2(acc1[i], ap, wv[2*kk+1]);
                }
            }
        }
        #pragma unroll
        for (int i = 0; i < 4; i++) {
            float4 o;
            unpack2(acc0[i], o.x, o.y);
            unpack2(acc1[i], o.z, o.w);
            *reinterpret_cast<float4*>(&g_xf[(base + n0 + i) * NF + j0]) = o;
        }
        __syncthreads();
    }
}

// ---------------------------------------------------------------------------
// Kernel 4: fused edge kernel — R6 math (float4 a-loads + pack_rep2 FFMA2),
// but 1024 threads = 32 warps * 4 edges -> occupancy 2x for latency hiding.
// 128 edges/tile, warp-autonomous, v4 RED scatter.
// ---------------------------------------------------------------------------
#define TILE_E 128
__global__ __launch_bounds__(1024, 1)
void edge_kernel(const int* __restrict__ edge_index,
                 const float* __restrict__ edge_weight,
                 const float* __restrict__ edge_attr,
                 const float* __restrict__ mlp_w1,
                 const float* __restrict__ mlp_b1,
                 const float* __restrict__ mlp_w2,
                 const float* __restrict__ mlp_b2) {
    extern __shared__ float sm[];
    float* W1s    = sm;                 // 64*128   =  8192
    float* W2s    = W1s + 8192;         // 128*128  = 16384
    float* b1s    = W2s + 16384;        // 128
    float* b2s    = b1s + 128;          // 128
    float* attr_s = b2s + 128;          // 128*64   =  8192
    float* h_s    = attr_s + 8192;      // 128*128  = 16384
    float* Cs     = h_s + 16384;        // 128
    int*   srcs   = (int*)(Cs + 128);   // 128
    int*   dsts   = srcs + 128;         // 128
    // total 49792 floats = 199168 B

    const int tid  = threadIdx.x;
    const int lane = tid & 31;
    const int wrp  = tid >> 5;          // 0..31
    const int e0   = wrp * 4;           // this warp's 4 edges within tile

    for (int i = tid; i < 8192 / 4; i += 1024)
        reinterpret_cast<float4*>(W1s)[i] = reinterpret_cast<const float4*>(mlp_w1)[i];
    for (int i = tid; i < 16384 / 4; i += 1024)
        reinterpret_cast<float4*>(W2s)[i] = reinterpret_cast<const float4*>(mlp_w2)[i];
    if (tid < 128) { b1s[tid] = mlp_b1[tid]; b2s[tid] = mlp_b2[tid]; }
    __syncthreads();

    const int j0 = lane * 4;
    float* my_attr = attr_s + e0 * NUM_RBF;   // 4x64 slice
    float* my_h    = h_s    + e0 * NF;        // 4x128 slice

    const float4 b1v = *reinterpret_cast<const float4*>(&b1s[j0]);
    const float4 b2v = *reinterpret_cast<const float4*>(&b2s[j0]);

    const int n_tiles = N_EDGES / TILE_E;   // 12500
    for (int t = blockIdx.x; t < n_tiles; t += gridDim.x) {
        const int base = t * TILE_E + e0;   // first edge of this warp's group

        if (lane < 4) {
            int e = base + lane;
            srcs[e0 + lane] = clamp_idx(edge_index[e]);
            dsts[e0 + lane] = clamp_idx(edge_index[N_EDGES + e]);
            float w = edge_weight[e];
            float c = 0.5f * (__cosf(w * (PI_F / CUTOFF)) + 1.0f);
            Cs[e0 + lane] = (w < CUTOFF) ? c : 0.0f;
        }
        // 4 rows x 64 floats = 64 float4 -> 2 per lane, coalesced
        {
            const float4* gsrc = reinterpret_cast<const float4*>(edge_attr + (size_t)base * NUM_RBF);
            float4* ssrc = reinterpret_cast<float4*>(my_attr);
            ssrc[lane]      = gsrc[lane];
            ssrc[lane + 32] = gsrc[lane + 32];
        }
        __syncwarp();

        // ---- phase 1: h = silu(attr @ W1 + b1) ----
        u64 acc0[4], acc1[4];
        #pragma unroll
        for (int i = 0; i < 4; i++) { acc0[i] = 0ull; acc1[i] = 0ull; }

        #pragma unroll 4
        for (int k4 = 0; k4 < NUM_RBF / 4; k4++) {
            float4 a4[4];
            #pragma unroll
            for (int i = 0; i < 4; i++)
                a4[i] = *reinterpret_cast<const float4*>(&my_attr[i * NUM_RBF + k4 * 4]);
            #pragma unroll
            for (int kk = 0; kk < 4; kk++) {
                const int k = k4 * 4 + kk;
                u64 w01, w23;
                lds_v2u64(&W1s[k * NF + j0], w01, w23);
                #pragma unroll
                for (int i = 0; i < 4; i++) {
                    float a = (kk == 0) ? a4[i].x : (kk == 1) ? a4[i].y
                             : (kk == 2) ? a4[i].z : a4[i].w;
                    u64 ap = pack_rep2(a);
                    fma2(acc0[i], ap, w01);
                    fma2(acc1[i], ap, w23);
                }
            }
        }
        #pragma unroll
        for (int i = 0; i < 4; i++) {
            float p0, p1, p2, p3;
            unpack2(acc0[i], p0, p1);
            unpack2(acc1[i], p2, p3);
            float4 h4;
            h4.x = silu_f(p0 + b1v.x);
            h4.y = silu_f(p1 + b1v.y);
            h4.z = silu_f(p2 + b1v.z);
            h4.w = silu_f(p3 + b1v.w);
            *reinterpret_cast<float4*>(&my_h[i * NF + j0]) = h4;
        }
        __syncwarp();

        // ---- phase 2: W = (h @ W2 + b2) * C ; gather * W ; scatter ----
        #pragma unroll
        for (int i = 0; i < 4; i++) { acc0[i] = 0ull; acc1[i] = 0ull; }

        #pragma unroll 4
        for (int k4 = 0; k4 < NF / 4; k4++) {
            float4 a4[4];
            #pragma unroll
            for (int i = 0; i < 4; i++)
                a4[i] = *reinterpret_cast<const float4*>(&my_h[i * NF + k4 * 4]);
            #pragma unroll
            for (int kk = 0; kk < 4; kk++) {
                const int k = k4 * 4 + kk;
                u64 w01, w23;
                lds_v2u64(&W2s[k * NF + j0], w01, w23);
                #pragma unroll
                for (int i = 0; i < 4; i++) {
                    float a = (kk == 0) ? a4[i].x : (kk == 1) ? a4[i].y
                             : (kk == 2) ? a4[i].z : a4[i].w;
                    u64 ap = pack_rep2(a);
                    fma2(acc0[i], ap, w01);
                    fma2(acc1[i], ap, w23);
                }
            }
        }

        #pragma unroll
        for (int i = 0; i < 4; i++) {
            const float c = Cs[e0 + i];
            const int s = srcs[e0 + i];
            const int d = dsts[e0 + i];
            float p0, p1, p2, p3;
            unpack2(acc0[i], p0, p1);
            unpack2(acc1[i], p2, p3);
            float4 xf4 = *reinterpret_cast<const float4*>(&g_xf[s * NF + j0]);
            red_add_v4(&g_agg[d * NF + j0],
                       (p0 + b2v.x) * c * xf4.x,
                       (p1 + b2v.y) * c * xf4.y,
                       (p2 + b2v.z) * c * xf4.z,
                       (p3 + b2v.w) * c * xf4.w);
        }
        __syncwarp();
    }
}

// ---------------------------------------------------------------------------
// Kernel 5: node tail (FFMA2, R9 version)
// ---------------------------------------------------------------------------
__global__ void node_kernel(const float* __restrict__ lin2_w,
                            const float* __restrict__ lin2_b,
                            const float* __restrict__ lin_w,
                            const float* __restrict__ lin_b,
                            float* __restrict__ out) {
    extern __shared__ float sm[];
    float* L2s = sm;
    float* Ls  = L2s + 16384;
    float* b2s = Ls + 16384;
    float* bs  = b2s + 128;
    float* a_s = bs + 128;
    float* t_s = a_s + 8192;

    const int tid = threadIdx.x;
    for (int i = tid; i < 16384 / 4; i += 512) {
        reinterpret_cast<float4*>(L2s)[i] = reinterpret_cast<const float4*>(lin2_w)[i];
        reinterpret_cast<float4*>(Ls)[i]  = reinterpret_cast<const float4*>(lin_w)[i];
    }
    if (tid < 128) { b2s[tid] = lin2_b[tid]; bs[tid] = lin_b[tid]; }
    __syncthreads();

    const int j0 = (tid & 31) * 4;
    const int n0 = (tid >> 5) * 4;

    const int n_tiles = (N_NODES + 63) / 64;
    for (int t = blockIdx.x; t < n_tiles; t += gridDim.x) {
        const int base = t * 64;

        for (int i = tid; i < 64 * 32; i += 512) {
            int r = i >> 5, cg = i & 31, n = base + r;
            float4 v = make_float4(0.f, 0.f, 0.f, 0.f);
            if (n < N_NODES) {
                v = *reinterpret_cast<const float4*>(&g_agg[n * NF + cg * 4]);
                float inv = 1.0f / fmaxf(g_cnt[n], 1.0f);
                v.x *= inv; v.y *= inv; v.z *= inv; v.w *= inv;
            }
            *reinterpret_cast<float4*>(&a_s[r * NF + cg * 4]) = v;
        }
        __syncthreads();

        u64 acc0[4], acc1[4];
        #pragma unroll
        for (int i = 0; i < 4; i++) { acc0[i] = 0ull; acc1[i] = 0ull; }
        #pragma unroll 4
        for (int k4 = 0; k4 < NF / 4; k4++) {
            u64 wv[8];
            #pragma unroll
            for (int kk = 0; kk < 4; kk++)
                lds_v2u64(&L2s[(k4 * 4 + kk) * HIDDEN + j0], wv[2*kk], wv[2*kk+1]);
            float4 a4[4];
            #pragma unroll
            for (int i = 0; i < 4; i++)
                a4[i] = *reinterpret_cast<const float4*>(&a_s[(n0 + i) * NF + k4 * 4]);
            #pragma unroll
            for (int kk = 0; kk < 4; kk++) {
                #pragma unroll
                for (int i = 0; i < 4; i++) {
                    float a = (kk == 0) ? a4[i].x : (kk == 1) ? a4[i].y
                             : (kk == 2) ? a4[i].z : a4[i].w;
                    u64 ap = pack_rep2(a);
                    fma2(acc0[i], ap, wv[2*kk]);
                    fma2(acc1[i], ap, wv[2*kk+1]);
                }
            }
        }
        {
            float4 bv = *reinterpret_cast<const float4*>(&b2s[j0]);
            #pragma unroll
            for (int i = 0; i < 4; i++) {
                float p0, p1, p2, p3;
                unpack2(acc0[i], p0, p1);
                unpack2(acc1[i], p2, p3);
                float4 h4;
                h4.x = silu_f(p0 + bv.x);
                h4.y = silu_f(p1 + bv.y);
                h4.z = silu_f(p2 + bv.z);
                h4.w = silu_f(p3 + bv.w);
                *reinterpret_cast<float4*>(&t_s[(n0 + i) * HIDDEN + j0]) = h4;
            }
        }
        __syncthreads();

        #pragma unroll
        for (int i = 0; i < 4; i++) { acc0[i] = 0ull; acc1[i] = 0ull; }
        #pragma unroll 4
        for (int k4 = 0; k4 < HIDDEN / 4; k4++) {
            u64 wv[8];
            #pragma unroll
            for (int kk = 0; kk < 4; kk++)
                lds_v2u64(&Ls[(k4 * 4 + kk) * HIDDEN + j0], wv[2*kk], wv[2*kk+1]);
            float4 a4[4];
            #pragma unroll
            for (int i = 0; i < 4; i++)
                a4[i] = *reinterpret_cast<const float4*>(&t_s[(n0 + i) * HIDDEN + k4 * 4]);
            #pragma unroll
            for (int kk = 0; kk < 4; kk++) {
                #pragma unroll
                for (int i = 0; i < 4; i++) {
                    float a = (kk == 0) ? a4[i].x : (kk == 1) ? a4[i].y
                             : (kk == 2) ? a4[i].z : a4[i].w;
                    u64 ap = pack_rep2(a);
                    fma2(acc0[i], ap, wv[2*kk]);
                    fma2(acc1[i], ap, wv[2*kk+1]);
                }
            }
        }
        {
            float4 bv = *reinterpret_cast<const float4*>(&bs[j0]);
            #pragma unroll
            for (int i = 0; i < 4; i++) {
                int n = base + n0 + i;
                if (n < N_NODES) {
                    float p0, p1, p2, p3;
                    unpack2(acc0[i], p0, p1);
                    unpack2(acc1[i], p2, p3);
                    float4 o;
                    o.x = p0 + bv.x; o.y = p1 + bv.y;
                    o.z = p2 + bv.z; o.w = p3 + bv.w;
                    *reinterpret_cast<float4*>(&out[n * HIDDEN + j0]) = o;
                }
            }
        }
        __syncthreads();
    }
}

// ---------------------------------------------------------------------------
// launch
// ---------------------------------------------------------------------------
extern "C" void kernel_launch(void* const* d_in, const int* in_sizes, int n_in,
                              void* d_out, int out_size) {
    const float* x   = (const float*)d_in[0];
    const int*   ei  = (const int*)d_in[1];      // int32 (JAX x64 disabled)
    const float* ew  = (const float*)d_in[2];
    const float* ea  = (const float*)d_in[3];
    const float* w1  = (const float*)d_in[4];
    const float* b1  = (const float*)d_in[5];
    const float* w2  = (const float*)d_in[6];
    const float* b2  = (const float*)d_in[7];
    const float* l1w = (const float*)d_in[8];
    const float* l2w = (const float*)d_in[9];
    const float* l2b = (const float*)d_in[10];
    const float* lw  = (const float*)d_in[11];
    const float* lb  = (const float*)d_in[12];
    float* out = (float*)d_out;

    const int smem_xf   = (16384 + 4096) * 4;
    const int smem_edge = 49792 * 4;
    const int smem_node = 49408 * 4;
    cudaFuncSetAttribute(xf_kernel,   cudaFuncAttributeMaxDynamicSharedMemorySize, smem_xf);
    cudaFuncSetAttribute(edge_kernel, cudaFuncAttributeMaxDynamicSharedMemorySize, smem_edge);
    cudaFuncSetAttribute(node_kernel, cudaFuncAttributeMaxDynamicSharedMemorySize, smem_node);

    zero_kernel<<<1024, 256>>>();
    cnt_kernel<<<2048, 256>>>(ei);
    xf_kernel<<<296, 256, smem_xf>>>(x, l1w);
    edge_kernel<<<148, 1024, smem_edge>>>(ei, ew, ea, w1, b1, w2, b2);
    node_kernel<<<148, 512, smem_node>>>(l2w, l2b, lw, lb, out);
}

// round 15
// speedup vs baseline: 1.7584x; 1.7584x over previous
#include <cuda_runtime.h>
#include <math.h>
#include <stdint.h>

#define N_NODES   100000
#define N_EDGES   1600000
#define HIDDEN    128
#define NUM_RBF   64
#define NF        128
#define CUTOFF    5.0f
#define PI_F      3.14159265358979323846f

typedef unsigned long long u64;

// ---------------------------------------------------------------------------
// Scratch
// ---------------------------------------------------------------------------
__device__ __align__(16) float g_xf [N_NODES * NF];
__device__ __align__(16) float g_agg[N_NODES * NF];
__device__ float g_cnt[N_NODES];

__device__ __forceinline__ float silu_f(float v) {
    return v / (1.0f + __expf(-v));
}
__device__ __forceinline__ int clamp_idx(int v) {
    v = v < 0 ? 0 : v;
    return v >= N_NODES ? N_NODES - 1 : v;
}

// ---- f32x2 helpers ----
__device__ __forceinline__ u64 pack_rep2(float a) {
    u64 r;
    asm("mov.b64 %0, {%1, %1};" : "=l"(r) : "f"(a));
    return r;
}
__device__ __forceinline__ void fma2(u64& d, u64 a, u64 b) {
    asm("fma.rn.f32x2 %0, %1, %2, %0;" : "+l"(d) : "l"(a), "l"(b));
}
__device__ __forceinline__ void unpack2(u64 v, float& lo, float& hi) {
    asm("mov.b64 {%0, %1}, %2;" : "=f"(lo), "=f"(hi) : "l"(v));
}
__device__ __forceinline__ void lds_v2u64(const void* p, u64& x, u64& y) {
    uint32_t addr = (uint32_t)__cvta_generic_to_shared(p);
    asm("ld.shared.v2.u64 {%0, %1}, [%2];" : "=l"(x), "=l"(y) : "r"(addr));
}
__device__ __forceinline__ void red_add_v4(float* addr, float a, float b,
                                           float c, float d) {
    asm volatile("red.global.add.v4.f32 [%0], {%1, %2, %3, %4};"
                 :: "l"(addr), "f"(a), "f"(b), "f"(c), "f"(d)
                 : "memory");
}

// ---------------------------------------------------------------------------
// Kernel 1: zero agg + cnt
// ---------------------------------------------------------------------------
__global__ void zero_kernel() {
    int idx = blockIdx.x * blockDim.x + threadIdx.x;
    int stride = gridDim.x * blockDim.x;
    float4* agg4 = reinterpret_cast<float4*>(g_agg);
    const int n4 = N_NODES * (NF / 4);
    float4 z = make_float4(0.f, 0.f, 0.f, 0.f);
    for (int i = idx; i < n4; i += stride) agg4[i] = z;
    for (int i = idx; i < N_NODES; i += stride) g_cnt[i] = 0.f;
}

// ---------------------------------------------------------------------------
// Kernel 2: in-degree counts
// ---------------------------------------------------------------------------
__global__ void cnt_kernel(const int* __restrict__ edge_index) {
    int idx = blockIdx.x * blockDim.x + threadIdx.x;
    int stride = gridDim.x * blockDim.x;
    for (int e = idx; e < N_EDGES; e += stride) {
        int d = clamp_idx(edge_index[N_EDGES + e]);
        atomicAdd(&g_cnt[d], 1.0f);
    }
}

// ---------------------------------------------------------------------------
// Kernel 3: xf = x @ lin1_w   (FFMA2)
// ---------------------------------------------------------------------------
__global__ void xf_kernel(const float* __restrict__ x,
                          const float* __restrict__ lin1_w) {
    extern __shared__ float sm[];
    float* ws = sm;            // 128*128
    float* xs = ws + 16384;    // 32*128

    const int tid = threadIdx.x;
    for (int i = tid; i < 16384 / 4; i += 256)
        reinterpret_cast<float4*>(ws)[i] = reinterpret_cast<const float4*>(lin1_w)[i];
    __syncthreads();

    const int j0 = (tid & 31) * 4;
    const int n0 = (tid >> 5) * 4;

    const int n_tiles = N_NODES / 32;
    for (int t = blockIdx.x; t < n_tiles; t += gridDim.x) {
        const int base = t * 32;
        for (int i = tid; i < 32 * 32; i += 256)
            reinterpret_cast<float4*>(xs)[i] =
                reinterpret_cast<const float4*>(x + base * HIDDEN)[i];
        __syncthreads();

        u64 acc0[4], acc1[4];
        #pragma unroll
        for (int i = 0; i < 4; i++) { acc0[i] = 0ull; acc1[i] = 0ull; }

        #pragma unroll 4
        for (int k4 = 0; k4 < HIDDEN / 4; k4++) {
            u64 wv[8];
            #pragma unroll
            for (int kk = 0; kk < 4; kk++)
                lds_v2u64(&ws[(k4 * 4 + kk) * NF + j0], wv[2*kk], wv[2*kk+1]);
            float4 a4[4];
            #pragma unroll
            for (int i = 0; i < 4; i++)
                a4[i] = *reinterpret_cast<const float4*>(&xs[(n0 + i) * HIDDEN + k4 * 4]);
            #pragma unroll
            for (int kk = 0; kk < 4; kk++) {
                #pragma unroll
                for (int i = 0; i < 4; i++) {
                    float a = (kk == 0) ? a4[i].x : (kk == 1) ? a4[i].y
                             : (kk == 2) ? a4[i].z : a4[i].w;
                    u64 ap = pack_rep2(a);
                    fma2(acc0[i], ap, wv[2*kk]);
                    fma2(acc1[i], ap, wv[2*kk+1]);
                }
            }
        }
        #pragma unroll
        for (int i = 0; i < 4; i++) {
            float4 o;
            unpack2(acc0[i], o.x, o.y);
            unpack2(acc1[i], o.z, o.w);
            *reinterpret_cast<float4*>(&g_xf[(base + n0 + i) * NF + j0]) = o;
        }
        __syncthreads();
    }
}

// ---------------------------------------------------------------------------
// Kernel 4: fused edge kernel — R6 math, 20 warps x 8 edges = 160-edge tiles.
// Inner 8-edge loop split into two 4-edge waves to lower live registers
// (640-thread cap ~102 regs/thread).
// ---------------------------------------------------------------------------
#define TILE_E 160
#define NTHR   640
__global__ __launch_bounds__(NTHR, 1)
void edge_kernel(const int* __restrict__ edge_index,
                 const float* __restrict__ edge_weight,
                 const float* __restrict__ edge_attr,
                 const float* __restrict__ mlp_w1,
                 const float* __restrict__ mlp_b1,
                 const float* __restrict__ mlp_w2,
                 const float* __restrict__ mlp_b2) {
    extern __shared__ float sm[];
    float* W1s    = sm;                   // 64*128   =  8192
    float* W2s    = W1s + 8192;           // 128*128  = 16384
    float* b1s    = W2s + 16384;          // 128
    float* b2s    = b1s + 128;            // 128
    float* attr_s = b2s + 128;            // 160*64   = 10240
    float* h_s    = attr_s + 10240;       // 160*128  = 20480
    float* Cs     = h_s + 20480;          // 160
    int*   srcs   = (int*)(Cs + 160);     // 160
    int*   dsts   = srcs + 160;           // 160
    // total 56032 floats = 224128 B

    const int tid  = threadIdx.x;
    const int lane = tid & 31;
    const int wrp  = tid >> 5;            // 0..19
    const int e0   = wrp * 8;

    for (int i = tid; i < 8192 / 4; i += NTHR)
        reinterpret_cast<float4*>(W1s)[i] = reinterpret_cast<const float4*>(mlp_w1)[i];
    for (int i = tid; i < 16384 / 4; i += NTHR)
        reinterpret_cast<float4*>(W2s)[i] = reinterpret_cast<const float4*>(mlp_w2)[i];
    if (tid < 128) { b1s[tid] = mlp_b1[tid]; b2s[tid] = mlp_b2[tid]; }
    __syncthreads();

    const int j0 = lane * 4;
    float* my_attr = attr_s + e0 * NUM_RBF;
    float* my_h    = h_s    + e0 * NF;

    const float4 b1v = *reinterpret_cast<const float4*>(&b1s[j0]);
    const float4 b2v = *reinterpret_cast<const float4*>(&b2s[j0]);

    const int n_tiles = N_EDGES / TILE_E;   // 10000 exact
    for (int t = blockIdx.x; t < n_tiles; t += gridDim.x) {
        const int base = t * TILE_E + e0;

        if (lane < 8) {
            int e = base + lane;
            srcs[e0 + lane] = clamp_idx(edge_index[e]);
            dsts[e0 + lane] = clamp_idx(edge_index[N_EDGES + e]);
            float w = edge_weight[e];
            float c = 0.5f * (__cosf(w * (PI_F / CUTOFF)) + 1.0f);
            Cs[e0 + lane] = (w < CUTOFF) ? c : 0.0f;
        }
        {
            const float4* gsrc = reinterpret_cast<const float4*>(edge_attr + (size_t)base * NUM_RBF);
            float4* ssrc = reinterpret_cast<float4*>(my_attr);
            #pragma unroll
            for (int i = 0; i < 4; i++)
                ssrc[lane + 32 * i] = gsrc[lane + 32 * i];
        }
        __syncwarp();

        // ---- phase 1: h = silu(attr @ W1 + b1) ----
        u64 acc0[8], acc1[8];
        #pragma unroll
        for (int i = 0; i < 8; i++) { acc0[i] = 0ull; acc1[i] = 0ull; }

        #pragma unroll 4
        for (int k4 = 0; k4 < NUM_RBF / 4; k4++) {
            u64 w01[4], w23[4];
            #pragma unroll
            for (int kk = 0; kk < 4; kk++)
                lds_v2u64(&W1s[(k4 * 4 + kk) * NF + j0], w01[kk], w23[kk]);
            // two 4-edge waves to cap live registers
            #pragma unroll
            for (int g = 0; g < 2; g++) {
                float4 a4[4];
                #pragma unroll
                for (int i = 0; i < 4; i++)
                    a4[i] = *reinterpret_cast<const float4*>(
                        &my_attr[(g * 4 + i) * NUM_RBF + k4 * 4]);
                #pragma unroll
                for (int kk = 0; kk < 4; kk++) {
                    #pragma unroll
                    for (int i = 0; i < 4; i++) {
                        float a = (kk == 0) ? a4[i].x : (kk == 1) ? a4[i].y
                                 : (kk == 2) ? a4[i].z : a4[i].w;
                        u64 ap = pack_rep2(a);
                        fma2(acc0[g * 4 + i], ap, w01[kk]);
                        fma2(acc1[g * 4 + i], ap, w23[kk]);
                    }
                }
            }
        }
        #pragma unroll
        for (int i = 0; i < 8; i++) {
            float p0, p1, p2, p3;
            unpack2(acc0[i], p0, p1);
            unpack2(acc1[i], p2, p3);
            float4 h4;
            h4.x = silu_f(p0 + b1v.x);
            h4.y = silu_f(p1 + b1v.y);
            h4.z = silu_f(p2 + b1v.z);
            h4.w = silu_f(p3 + b1v.w);
            *reinterpret_cast<float4*>(&my_h[i * NF + j0]) = h4;
        }
        __syncwarp();

        // ---- phase 2: W = (h @ W2 + b2) * C ; gather * W ; scatter ----
        #pragma unroll
        for (int i = 0; i < 8; i++) { acc0[i] = 0ull; acc1[i] = 0ull; }

        #pragma unroll 4
        for (int k4 = 0; k4 < NF / 4; k4++) {
            u64 w01[4], w23[4];
            #pragma unroll
            for (int kk = 0; kk < 4; kk++)
                lds_v2u64(&W2s[(k4 * 4 + kk) * NF + j0], w01[kk], w23[kk]);
            #pragma unroll
            for (int g = 0; g < 2; g++) {
                float4 a4[4];
                #pragma unroll
                for (int i = 0; i < 4; i++)
                    a4[i] = *reinterpret_cast<const float4*>(
                        &my_h[(g * 4 + i) * NF + k4 * 4]);
                #pragma unroll
                for (int kk = 0; kk < 4; kk++) {
                    #pragma unroll
                    for (int i = 0; i < 4; i++) {
                        float a = (kk == 0) ? a4[i].x : (kk == 1) ? a4[i].y
                                 : (kk == 2) ? a4[i].z : a4[i].w;
                        u64 ap = pack_rep2(a);
                        fma2(acc0[g * 4 + i], ap, w01[kk]);
                        fma2(acc1[g * 4 + i], ap, w23[kk]);
                    }
                }
            }
        }

        #pragma unroll
        for (int i = 0; i < 8; i++) {
            const float c = Cs[e0 + i];
            const int s = srcs[e0 + i];
            const int d = dsts[e0 + i];
            float p0, p1, p2, p3;
            unpack2(acc0[i], p0, p1);
            unpack2(acc1[i], p2, p3);
            float4 xf4 = *reinterpret_cast<const float4*>(&g_xf[s * NF + j0]);
            red_add_v4(&g_agg[d * NF + j0],
                       (p0 + b2v.x) * c * xf4.x,
                       (p1 + b2v.y) * c * xf4.y,
                       (p2 + b2v.z) * c * xf4.z,
                       (p3 + b2v.w) * c * xf4.w);
        }
        __syncwarp();
    }
}

// ---------------------------------------------------------------------------
// Kernel 5: node tail (FFMA2)
// ---------------------------------------------------------------------------
__global__ void node_kernel(const float* __restrict__ lin2_w,
                            const float* __restrict__ lin2_b,
                            const float* __restrict__ lin_w,
                            const float* __restrict__ lin_b,
                            float* __restrict__ out) {
    extern __shared__ float sm[];
    float* L2s = sm;
    float* Ls  = L2s + 16384;
    float* b2s = Ls + 16384;
    float* bs  = b2s + 128;
    float* a_s = bs + 128;
    float* t_s = a_s + 8192;

    const int tid = threadIdx.x;
    for (int i = tid; i < 16384 / 4; i += 512) {
        reinterpret_cast<float4*>(L2s)[i] = reinterpret_cast<const float4*>(lin2_w)[i];
        reinterpret_cast<float4*>(Ls)[i]  = reinterpret_cast<const float4*>(lin_w)[i];
    }
    if (tid < 128) { b2s[tid] = lin2_b[tid]; bs[tid] = lin_b[tid]; }
    __syncthreads();

    const int j0 = (tid & 31) * 4;
    const int n0 = (tid >> 5) * 4;

    const int n_tiles = (N_NODES + 63) / 64;
    for (int t = blockIdx.x; t < n_tiles; t += gridDim.x) {
        const int base = t * 64;

        for (int i = tid; i < 64 * 32; i += 512) {
            int r = i >> 5, cg = i & 31, n = base + r;
            float4 v = make_float4(0.f, 0.f, 0.f, 0.f);
            if (n < N_NODES) {
                v = *reinterpret_cast<const float4*>(&g_agg[n * NF + cg * 4]);
                float inv = 1.0f / fmaxf(g_cnt[n], 1.0f);
                v.x *= inv; v.y *= inv; v.z *= inv; v.w *= inv;
            }
            *reinterpret_cast<float4*>(&a_s[r * NF + cg * 4]) = v;
        }
        __syncthreads();

        u64 acc0[4], acc1[4];
        #pragma unroll
        for (int i = 0; i < 4; i++) { acc0[i] = 0ull; acc1[i] = 0ull; }
        #pragma unroll 4
        for (int k4 = 0; k4 < NF / 4; k4++) {
            u64 wv[8];
            #pragma unroll
            for (int kk = 0; kk < 4; kk++)
                lds_v2u64(&L2s[(k4 * 4 + kk) * HIDDEN + j0], wv[2*kk], wv[2*kk+1]);
            float4 a4[4];
            #pragma unroll
            for (int i = 0; i < 4; i++)
                a4[i] = *reinterpret_cast<const float4*>(&a_s[(n0 + i) * NF + k4 * 4]);
            #pragma unroll
            for (int kk = 0; kk < 4; kk++) {
                #pragma unroll
                for (int i = 0; i < 4; i++) {
                    float a = (kk == 0) ? a4[i].x : (kk == 1) ? a4[i].y
                             : (kk == 2) ? a4[i].z : a4[i].w;
                    u64 ap = pack_rep2(a);
                    fma2(acc0[i], ap, wv[2*kk]);
                    fma2(acc1[i], ap, wv[2*kk+1]);
                }
            }
        }
        {
            float4 bv = *reinterpret_cast<const float4*>(&b2s[j0]);
            #pragma unroll
            for (int i = 0; i < 4; i++) {
                float p0, p1, p2, p3;
                unpack2(acc0[i], p0, p1);
                unpack2(acc1[i], p2, p3);
                float4 h4;
                h4.x = silu_f(p0 + bv.x);
                h4.y = silu_f(p1 + bv.y);
                h4.z = silu_f(p2 + bv.z);
                h4.w = silu_f(p3 + bv.w);
                *reinterpret_cast<float4*>(&t_s[(n0 + i) * HIDDEN + j0]) = h4;
            }
        }
        __syncthreads();

        #pragma unroll
        for (int i = 0; i < 4; i++) { acc0[i] = 0ull; acc1[i] = 0ull; }
        #pragma unroll 4
        for (int k4 = 0; k4 < HIDDEN / 4; k4++) {
            u64 wv[8];
            #pragma unroll
            for (int kk = 0; kk < 4; kk++)
                lds_v2u64(&Ls[(k4 * 4 + kk) * HIDDEN + j0], wv[2*kk], wv[2*kk+1]);
            float4 a4[4];
            #pragma unroll
            for (int i = 0; i < 4; i++)
                a4[i] = *reinterpret_cast<const float4*>(&t_s[(n0 + i) * HIDDEN + k4 * 4]);
            #pragma unroll
            for (int kk = 0; kk < 4; kk++) {
                #pragma unroll
                for (int i = 0; i < 4; i++) {
                    float a = (kk == 0) ? a4[i].x : (kk == 1) ? a4[i].y
                             : (kk == 2) ? a4[i].z : a4[i].w;
                    u64 ap = pack_rep2(a);
                    fma2(acc0[i], ap, wv[2*kk]);
                    fma2(acc1[i], ap, wv[2*kk+1]);
                }
            }
        }
        {
            float4 bv = *reinterpret_cast<const float4*>(&bs[j0]);
            #pragma unroll
            for (int i = 0; i < 4; i++) {
                int n = base + n0 + i;
                if (n < N_NODES) {
                    float p0, p1, p2, p3;
                    unpack2(acc0[i], p0, p1);
                    unpack2(acc1[i], p2, p3);
                    float4 o;
                    o.x = p0 + bv.x; o.y = p1 + bv.y;
                    o.z = p2 + bv.z; o.w = p3 + bv.w;
                    *reinterpret_cast<float4*>(&out[n * HIDDEN + j0]) = o;
                }
            }
        }
        __syncthreads();
    }
}

// ---------------------------------------------------------------------------
// launch
// ---------------------------------------------------------------------------
extern "C" void kernel_launch(void* const* d_in, const int* in_sizes, int n_in,
                              void* d_out, int out_size) {
    const float* x   = (const float*)d_in[0];
    const int*   ei  = (const int*)d_in[1];      // int32 (JAX x64 disabled)
    const float* ew  = (const float*)d_in[2];
    const float* ea  = (const float*)d_in[3];
    const float* w1  = (const float*)d_in[4];
    const float* b1  = (const float*)d_in[5];
    const float* w2  = (const float*)d_in[6];
    const float* b2  = (const float*)d_in[7];
    const float* l1w = (const float*)d_in[8];
    const float* l2w = (const float*)d_in[9];
    const float* l2b = (const float*)d_in[10];
    const float* lw  = (const float*)d_in[11];
    const float* lb  = (const float*)d_in[12];
    float* out = (float*)d_out;

    const int smem_xf   = (16384 + 4096) * 4;
    const int smem_edge = 56032 * 4;
    const int smem_node = 49408 * 4;
    cudaFuncSetAttribute(xf_kernel,   cudaFuncAttributeMaxDynamicSharedMemorySize, smem_xf);
    cudaFuncSetAttribute(edge_kernel, cudaFuncAttributeMaxDynamicSharedMemorySize, smem_edge);
    cudaFuncSetAttribute(node_kernel, cudaFuncAttributeMaxDynamicSharedMemorySize, smem_node);

    zero_kernel<<<1024, 256>>>();
    cnt_kernel<<<2048, 256>>>(ei);
    xf_kernel<<<296, 256, smem_xf>>>(x, l1w);
    edge_kernel<<<148, NTHR, smem_edge>>>(ei, ew, ea, w1, b1, w2, b2);
    node_kernel<<<148, 512, smem_node>>>(l2w, l2b, lw, lb, out);
}